// round 2
// baseline (speedup 1.0000x reference)
#include <cuda_runtime.h>
#include <cuda_bf16.h>

// ProdLayer: out[i] = prod_{j : csr[j]==i} x[ptrs[j]], empty segments -> 0.
// csr is sorted ascending, csr[E-1] == S-1, so segments are contiguous runs.
//
// Strategy: one thread per edge. Thread j is a "segment head" iff
// csr[j] != csr[j-1]. Heads zero-fill the gap of empty segment ids before
// them, then scan their run forward multiplying gathered x values.
// x (16 MB) fits in L2, so the random gather is L2-served after first touch.

__global__ void __launch_bounds__(256)
prod_layer_kernel(const float* __restrict__ x,
                  const int*   __restrict__ ptrs,
                  const int*   __restrict__ csr,
                  float*       __restrict__ out,
                  int E)
{
    int j = blockIdx.x * blockDim.x + threadIdx.x;
    if (j >= E) return;

    int cur  = csr[j];
    int prev = (j > 0) ? csr[j - 1] : -1;
    if (cur == prev) return;          // not a segment head

    // Zero-fill empty segment ids in (prev, cur). Covers the poisoned out
    // buffer for ids that receive no edges. Thread 0 covers [0, csr[0]).
    for (int i = prev + 1; i < cur; ++i) out[i] = 0.0f;

    // Product over the contiguous run [j, k) with csr == cur.
    float p = x[ptrs[j]];
    int k = j + 1;
    while (k < E && csr[k] == cur) {
        p *= x[ptrs[k]];
        ++k;
    }
    out[cur] = p;
}

extern "C" void kernel_launch(void* const* d_in, const int* in_sizes, int n_in,
                              void* d_out, int out_size)
{
    const float* x    = (const float*)d_in[0];
    const int*   ptrs = (const int*)  d_in[1];
    const int*   csr  = (const int*)  d_in[2];
    float*       out  = (float*)      d_out;

    int E = in_sizes[1];   // edges (len of ptrs == len of csr)

    int threads = 256;
    int blocks  = (E + threads - 1) / threads;
    prod_layer_kernel<<<blocks, threads>>>(x, ptrs, csr, out, E);
}

// round 4
// speedup vs baseline: 1.2329x; 1.2329x over previous
#include <cuda_runtime.h>
#include <cuda_bf16.h>

// ProdLayer: out[i] = prod_{j : csr[j]==i} x[ptrs[j]], empty segments -> 0.
// csr sorted ascending, csr[E-1] == S-1 => segments are contiguous runs.
//
// Warp-level segmented suffix product via shuffles. Each thread owns one
// edge; after 5 shfl_down steps, v_j = product of x[ptrs[k]] over the run
// containing j, from j to the run's end within this warp. Global segment
// heads (csr[j] != csr[j-1]) write the result. The (at most one) run per
// warp that spills past the warp boundary is finished serially by its head.
// Heads also zero-fill empty segment ids in the gap before them (out is
// poisoned, every element must be written).

__global__ void __launch_bounds__(256)
prod_seg_kernel(const float* __restrict__ x,
                const int*   __restrict__ ptrs,
                const int*   __restrict__ csr,
                float*       __restrict__ out,
                int E)
{
    const unsigned FULL = 0xffffffffu;
    int j    = blockIdx.x * blockDim.x + threadIdx.x;
    int lane = threadIdx.x & 31;
    bool valid = (j < E);

    // Out-of-range lanes get a sentinel key that matches nothing.
    int   key = valid ? __ldg(&csr[j]) : -2;
    float v   = valid ? __ldg(&x[__ldg(&ptrs[j])]) : 1.0f;

    // Segmented inclusive suffix product within the warp.
    // Keys are sorted, so (key[lane+d] == key[lane]) implies the whole span
    // [lane, lane+d] shares the key -> Hillis-Steele segmented scan is valid.
    #pragma unroll
    for (int d = 1; d < 32; d <<= 1) {
        int   k2 = __shfl_down_sync(FULL, key, d);
        float v2 = __shfl_down_sync(FULL, v,   d);
        if (lane + d < 32 && k2 == key) v *= v2;
    }

    // Head detection (do ALL shuffles before any divergent exit).
    int prevKey = __shfl_up_sync(FULL, key, 1);
    int key31   = __shfl_sync(FULL, key, 31);
    if (lane == 0) prevKey = (j > 0) ? __ldg(&csr[j - 1]) : -1;

    if (!valid || key == prevKey) return;   // not a global segment head

    // Zero-fill empty segment ids in (prevKey, key). Thread for j==0 covers
    // [0, csr[0]). Tail of out is covered because csr[E-1] == S-1.
    for (int i = prevKey + 1; i < key; ++i) out[i] = 0.0f;

    // If my run reaches lane 31 and continues past the warp, finish serially.
    // Only the last head in the warp can satisfy key31 == key.
    if (key31 == key) {
        int k = (j | 31) + 1;               // first edge after this warp
        while (k < E && __ldg(&csr[k]) == key) {
            v *= __ldg(&x[__ldg(&ptrs[k])]);
            ++k;
        }
    }

    out[key] = v;
}

extern "C" void kernel_launch(void* const* d_in, const int* in_sizes, int n_in,
                              void* d_out, int out_size)
{
    const float* x    = (const float*)d_in[0];
    const int*   ptrs = (const int*)  d_in[1];
    const int*   csr  = (const int*)  d_in[2];
    float*       out  = (float*)      d_out;

    int E = in_sizes[1];   // len(ptrs) == len(csr)

    int threads = 256;
    int blocks  = (E + threads - 1) / threads;
    prod_seg_kernel<<<blocks, threads>>>(x, ptrs, csr, out, E);
}

// round 5
// speedup vs baseline: 1.7772x; 1.4414x over previous
#include <cuda_runtime.h>
#include <cuda_bf16.h>

// ProdLayer: out[i] = prod_{j : csr[j]==i} x[ptrs[j]], empty segments -> 0.
// csr sorted ascending, csr[E-1] == S-1 => contiguous runs.
//
// R5: 4 edges per thread (int4 loads). In-thread runs folded in registers.
// Warp-level segmented suffix scan over per-thread aggregates:
//   kt = key of thread's last edge, s = product of trailing run in-thread,
//   G  = prefix-run product for key K0 over the current doubling window.
// Sortedness makes chain checks single key compares: k0[t+d]==key implies
// every edge in between shares that key.

__global__ void __launch_bounds__(256)
prod_seg4_kernel(const float* __restrict__ x,
                 const int*   __restrict__ ptrs,
                 const int*   __restrict__ csr,
                 float*       __restrict__ out,
                 int E)
{
    const unsigned FULL = 0xffffffffu;
    int t    = blockIdx.x * blockDim.x + threadIdx.x;
    int lane = threadIdx.x & 31;
    int b    = t << 2;                       // first edge of this thread
    bool valid = (b < E);

    int   K0 = -2, K1 = -2, K2 = -2, K3 = -2;
    float X0 = 1.f, X1 = 1.f, X2 = 1.f, X3 = 1.f;

    if (valid) {
        if (b + 3 < E) {
            int4 kk = *reinterpret_cast<const int4*>(csr  + b);
            int4 pp = *reinterpret_cast<const int4*>(ptrs + b);
            K0 = kk.x; K1 = kk.y; K2 = kk.z; K3 = kk.w;
            X0 = __ldg(&x[pp.x]); X1 = __ldg(&x[pp.y]);
            X2 = __ldg(&x[pp.z]); X3 = __ldg(&x[pp.w]);
        } else {                              // scalar tail (E%4 != 0)
            K0 = __ldg(&csr[b]);     X0 = __ldg(&x[__ldg(&ptrs[b])]);
            if (b+1 < E) { K1 = __ldg(&csr[b+1]); X1 = __ldg(&x[__ldg(&ptrs[b+1])]); }
            if (b+2 < E) { K2 = __ldg(&csr[b+2]); X2 = __ldg(&x[__ldg(&ptrs[b+2])]); }
        }
    }

    // Key of last valid edge in this thread (-2 if thread invalid).
    int kt = K3;
    if (kt == -2) kt = K2;
    if (kt == -2) kt = K1;
    if (kt == -2) kt = K0;

    // Trailing-run product within thread (keys == kt; sentinels never match a
    // valid kt; for invalid threads everything is 1).
    float s = (K3 == kt ? X3 : 1.f) * (K2 == kt ? X2 : 1.f)
            * (K1 == kt ? X1 : 1.f) * (K0 == kt ? X0 : 1.f);
    // Prefix-run product for key K0.
    float g = X0 * (K1 == K0 ? X1 : 1.f) * (K2 == K0 ? X2 : 1.f)
            * (K3 == K0 ? X3 : 1.f);

    // prev = key of edge b-1 (last key of previous thread).
    int prev = __shfl_up_sync(FULL, kt, 1);
    if (lane == 0) prev = (b > 0) ? __ldg(&csr[b - 1]) : -1;

    // Warp segmented suffix scan over thread aggregates.
    float V = s, G = g;
    #pragma unroll
    for (int d = 1; d < 32; d <<= 1) {
        int   kd = __shfl_down_sync(FULL, K0, d);   // original head key of t+d
        float Gd = __shfl_down_sync(FULL, G,  d);
        bool src = (lane + d) < 32;
        if (src && kd == kt) V *= Gd;   // my trailing run extends into t+d
        if (src && kd == K0) G *= Gd;   // prefix run spans whole window
    }

    int kLast = __shfl_sync(FULL, kt, 31);          // warp's last key

    // Cross-warp continuation: only the thread owning the HEAD of the warp's
    // trailing run runs it (one lane per warp at most).
    if (valid && (K0 != kt || prev != kt) && kt == kLast) {
        int e = b - (lane << 2) + 128;              // first edge after warp
        while (e < E && __ldg(&csr[e]) == kt) {
            V *= __ldg(&x[__ldg(&ptrs[e])]);
            ++e;
        }
    }

    if (!valid) return;

    // Emit heads: zero-fill gaps, interior runs from registers, trailing run
    // writes the scanned V.
    int   Ks[4] = {K0, K1, K2, K3};
    float Xs[4] = {X0, X1, X2, X3};
    int p = prev;
    #pragma unroll
    for (int m = 0; m < 4; ++m) {
        int km = Ks[m];
        if (km >= 0 && km != p) {
            for (int i = p + 1; i < km; ++i) out[i] = 0.0f;
            if (km == kt) {
                out[km] = V;                         // trailing run (w/ continuation)
            } else {
                float pr = Xs[m];
                #pragma unroll
                for (int mm = m + 1; mm < 4; ++mm)
                    if (Ks[mm] == km) pr *= Xs[mm];
                out[km] = pr;                        // fully interior run
            }
        }
        if (km >= 0) p = km;
    }
}

extern "C" void kernel_launch(void* const* d_in, const int* in_sizes, int n_in,
                              void* d_out, int out_size)
{
    const float* x    = (const float*)d_in[0];
    const int*   ptrs = (const int*)  d_in[1];
    const int*   csr  = (const int*)  d_in[2];
    float*       out  = (float*)      d_out;

    int E = in_sizes[1];
    int threads4 = (E + 3) / 4;
    int block = 256;
    int grid  = (threads4 + block - 1) / block;
    prod_seg4_kernel<<<grid, block>>>(x, ptrs, csr, out, E);
}

// round 6
// speedup vs baseline: 2.0780x; 1.1693x over previous
#include <cuda_runtime.h>
#include <cuda_bf16.h>

// ProdLayer: out[i] = prod_{j : csr[j]==i} x[ptrs[j]], empty segments -> 0.
// csr sorted ascending, csr[E-1] == S-1 => contiguous runs.
//
// R6: 8 edges per thread (2x int4 loads each for csr/ptrs). Per-thread
// suffix-run products P[m] resolve every in-thread run head in registers.
// Warp-level segmented suffix scan combines trailing runs across threads;
// at most one serial continuation per warp for the run spilling past it.

__global__ void __launch_bounds__(256)
prod_seg8_kernel(const float* __restrict__ x,
                 const int*   __restrict__ ptrs,
                 const int*   __restrict__ csr,
                 float*       __restrict__ out,
                 int E)
{
    const unsigned FULL = 0xffffffffu;
    int t    = blockIdx.x * blockDim.x + threadIdx.x;
    int lane = threadIdx.x & 31;
    int b    = t << 3;                        // first edge of this thread
    bool valid = (b < E);

    int   K[8];
    float X[8];
    #pragma unroll
    for (int m = 0; m < 8; ++m) { K[m] = -2; X[m] = 1.0f; }

    if (valid) {
        if (b + 7 < E) {
            int4 ka = *reinterpret_cast<const int4*>(csr  + b);
            int4 kb = *reinterpret_cast<const int4*>(csr  + b + 4);
            int4 pa = *reinterpret_cast<const int4*>(ptrs + b);
            int4 pb = *reinterpret_cast<const int4*>(ptrs + b + 4);
            K[0]=ka.x; K[1]=ka.y; K[2]=ka.z; K[3]=ka.w;
            K[4]=kb.x; K[5]=kb.y; K[6]=kb.z; K[7]=kb.w;
            X[0]=__ldg(&x[pa.x]); X[1]=__ldg(&x[pa.y]);
            X[2]=__ldg(&x[pa.z]); X[3]=__ldg(&x[pa.w]);
            X[4]=__ldg(&x[pb.x]); X[5]=__ldg(&x[pb.y]);
            X[6]=__ldg(&x[pb.z]); X[7]=__ldg(&x[pb.w]);
        } else {
            #pragma unroll
            for (int m = 0; m < 8; ++m) {
                if (b + m < E) {
                    K[m] = __ldg(&csr[b + m]);
                    X[m] = __ldg(&x[__ldg(&ptrs[b + m])]);
                }
            }
        }
    }

    // Key of last valid edge in this thread (-2 if none).
    int kt = -2;
    #pragma unroll
    for (int m = 0; m < 8; ++m) if (K[m] != -2) kt = K[m];

    // Suffix-run products: P[m] = prod of X from m to end of m's run
    // (within this thread). Sentinel positions have X=1 so they are inert.
    float P[8];
    P[7] = X[7];
    #pragma unroll
    for (int m = 6; m >= 0; --m)
        P[m] = X[m] * ((K[m + 1] == K[m]) ? P[m + 1] : 1.0f);

    // s = product of trailing run (first index with key kt). Select smallest m.
    float s = 1.0f;
    #pragma unroll
    for (int m = 7; m >= 0; --m) if (K[m] == kt) s = P[m];

    // g = prefix-run product for key K[0]; sortedness makes compares direct.
    float g = X[0];
    #pragma unroll
    for (int m = 1; m < 8; ++m) g *= (K[m] == K[0]) ? X[m] : 1.0f;

    // prev = key of edge b-1.
    int prev = __shfl_up_sync(FULL, kt, 1);
    if (lane == 0) prev = (b > 0) ? __ldg(&csr[b - 1]) : -1;

    // Warp segmented suffix scan over thread aggregates.
    int   K0 = K[0];
    float V = s, G = g;
    #pragma unroll
    for (int d = 1; d < 32; d <<= 1) {
        int   kd = __shfl_down_sync(FULL, K0, d);
        float Gd = __shfl_down_sync(FULL, G,  d);
        bool src = (lane + d) < 32;
        if (src && kd == kt) V *= Gd;     // trailing run extends into t+d
        if (src && kd == K0) G *= Gd;     // prefix run spans the window
    }

    int kLast = __shfl_sync(FULL, kt, 31);

    // Cross-warp continuation: only the head of the warp-trailing run.
    if (valid && (K0 != kt || prev != kt) && kt == kLast) {
        int e = b - (lane << 3) + 256;    // first edge after this warp
        while (e < E && __ldg(&csr[e]) == kt) {
            V *= __ldg(&x[__ldg(&ptrs[e])]);
            ++e;
        }
    }

    if (!valid) return;

    // Emit: for each in-thread run head, zero-fill the empty-id gap then
    // write the run product (trailing run uses scanned V).
    int p = prev;
    #pragma unroll
    for (int m = 0; m < 8; ++m) {
        int km = K[m];
        if (km >= 0 && km != p) {
            for (int i = p + 1; i < km; ++i) out[i] = 0.0f;
            out[km] = (km == kt) ? V : P[m];
        }
        if (km >= 0) p = km;
    }
}

extern "C" void kernel_launch(void* const* d_in, const int* in_sizes, int n_in,
                              void* d_out, int out_size)
{
    const float* x    = (const float*)d_in[0];
    const int*   ptrs = (const int*)  d_in[1];
    const int*   csr  = (const int*)  d_in[2];
    float*       out  = (float*)      d_out;

    int E = in_sizes[1];
    int threads8 = (E + 7) / 8;
    int block = 256;
    int grid  = (threads8 + block - 1) / block;
    prod_seg8_kernel<<<grid, block>>>(x, ptrs, csr, out, E);
}